// round 14
// baseline (speedup 1.0000x reference)
#include <cuda_runtime.h>
#include <cuda_fp16.h>
#include <cstdint>
#include <cmath>

#define T_SEQ   1024
#define D_MODEL 1024
#define NHEAD   16
#define HDIM    64
#define DFF     4096
#define BATCH   8
#define MROWS   (BATCH * T_SEQ)
#define QKV_N   (3 * D_MODEL)
#define MHALF   (MROWS / 2)

// ---------------- scratch (device globals: allocation-free) ----------------
__device__ __half g_h1 [(size_t)MROWS * D_MODEL];
__device__ __half g_qkv[(size_t)MROWS * QKV_N];
__device__ __half g_att[(size_t)MROWS * D_MODEL];
__device__ float  g_res[(size_t)MROWS * D_MODEL];
__device__ __half g_ff [(size_t)MROWS * DFF];
__device__ __half g_wqkvT[(size_t)QKV_N * D_MODEL];
__device__ __half g_woT[(size_t)D_MODEL * D_MODEL];
__device__ __half g_w1T[(size_t)DFF * D_MODEL];
__device__ __half g_w2T[(size_t)D_MODEL * DFF];

// ---------------- helpers ----------------
__device__ __forceinline__ uint32_t smem_u32(const void* p) {
    uint32_t a;
    asm("{ .reg .u64 t; cvta.to.shared.u64 t, %1; cvt.u32.u64 %0, t; }" : "=r"(a) : "l"(p));
    return a;
}
__device__ __forceinline__ float warp_sum(float v) {
#pragma unroll
    for (int o = 16; o > 0; o >>= 1) v += __shfl_xor_sync(0xffffffffu, v, o);
    return v;
}
__device__ __forceinline__ float fast_ex2(float x) {
    float y; asm("ex2.approx.f32 %0, %1;" : "=f"(y) : "f"(x)); return y;
}
__device__ __forceinline__ uint32_t h2ex2(uint32_t x) {
    uint32_t y; asm("ex2.approx.f16x2 %0, %1;" : "=r"(y) : "r"(x)); return y;
}
__device__ __forceinline__ float fast_tanh(float x) {
    float y; asm("tanh.approx.f32 %0, %1;" : "=f"(y) : "f"(x)); return y;
}
__device__ __forceinline__ float gelu_tanh(float x) {
    float x3 = x * x * x;
    float u  = 0.7978845608028654f * (x + 0.044715f * x3);
    return 0.5f * x * (1.0f + fast_tanh(u));
}
__device__ __forceinline__ void mma_f16(float* c, const uint32_t* a, uint32_t b0, uint32_t b1) {
    asm volatile(
        "mma.sync.aligned.m16n8k16.row.col.f32.f16.f16.f32 "
        "{%0,%1,%2,%3}, {%4,%5,%6,%7}, {%8,%9}, {%0,%1,%2,%3};\n"
        : "+f"(c[0]), "+f"(c[1]), "+f"(c[2]), "+f"(c[3])
        : "r"(a[0]), "r"(a[1]), "r"(a[2]), "r"(a[3]), "r"(b0), "r"(b1));
}
__device__ __forceinline__ void ldsm4(uint32_t* r, uint32_t addr) {
    asm volatile("ldmatrix.sync.aligned.m8n8.x4.shared.b16 {%0,%1,%2,%3}, [%4];"
        : "=r"(r[0]), "=r"(r[1]), "=r"(r[2]), "=r"(r[3]) : "r"(addr));
}
__device__ __forceinline__ uint32_t f22h2(float lo, float hi) {
    uint32_t u;
    asm("cvt.rn.f16x2.f32 %0, %1, %2;" : "=r"(u) : "f"(hi), "f"(lo));
    return u;
}
__device__ __forceinline__ void cp16(uint32_t dst, const void* src) {
    asm volatile("cp.async.cg.shared.global [%0], [%1], 16;" :: "r"(dst), "l"(src));
}
#define CP_COMMIT() asm volatile("cp.async.commit_group;" ::: "memory")
#define CP_WAIT0()  asm volatile("cp.async.wait_group 0;" ::: "memory")

// ---------------- weight transpose -> half: out[C][R] = (half)in[R][C] ----
__global__ __launch_bounds__(256) void transpose_h_kernel(
    const float* __restrict__ in, __half* __restrict__ out, int R, int C)
{
    __shared__ float t[32][33];
    const int bx = blockIdx.x * 32, by = blockIdx.y * 32;
    const int tx = threadIdx.x, ty = threadIdx.y;  // (32, 8)
#pragma unroll
    for (int i = 0; i < 4; i++)
        t[ty + 8 * i][tx] = in[(size_t)(by + ty + 8 * i) * C + bx + tx];
    __syncthreads();
#pragma unroll
    for (int i = 0; i < 4; i++)
        out[(size_t)(bx + ty + 8 * i) * R + by + tx] = __float2half_rn(t[tx][ty + 8 * i]);
}

// ---------------- LayerNorm: warp-per-row, shuffle-only reduction ----------
__global__ __launch_bounds__(256) void ln_kernel(
    const float* __restrict__ x, const float* __restrict__ sc,
    const float* __restrict__ bi, __half* __restrict__ y)
{
    const int wid = threadIdx.x >> 5, lane = threadIdx.x & 31;
    const int row = blockIdx.x * 8 + wid;

    const float4* xp = (const float4*)(x + (size_t)row * D_MODEL);
    float4 v[8];
#pragma unroll
    for (int i = 0; i < 8; i++) v[i] = xp[lane + 32 * i];

    float s = 0.f, q = 0.f;
#pragma unroll
    for (int i = 0; i < 8; i++) {
        s += v[i].x + v[i].y + v[i].z + v[i].w;
        q += v[i].x * v[i].x + v[i].y * v[i].y + v[i].z * v[i].z + v[i].w * v[i].w;
    }
    s = warp_sum(s);
    q = warp_sum(q);
    const float mean = s * (1.0f / 1024.0f);
    const float rstd = rsqrtf(q * (1.0f / 1024.0f) - mean * mean + 1e-6f);

    const float4* scp = (const float4*)sc;
    const float4* bip = (const float4*)bi;
    uint2* yp = (uint2*)(y + (size_t)row * D_MODEL);
#pragma unroll
    for (int i = 0; i < 8; i++) {
        float4 sv = scp[lane + 32 * i];
        float4 bv = bip[lane + 32 * i];
        uint2 o;
        o.x = f22h2((v[i].x - mean) * rstd * sv.x + bv.x,
                    (v[i].y - mean) * rstd * sv.y + bv.y);
        o.y = f22h2((v[i].z - mean) * rstd * sv.z + bv.z,
                    (v[i].w - mean) * rstd * sv.w + bv.w);
        yp[lane + 32 * i] = o;
    }
}

// ---------------- fp16 GEMM, 128x128 CTA, 2-stage cp.async, 1 sync/chunk ----
// (R9-winning configuration; operates on an M-slice via pointer offsets)
// EPI: 1 = f32 +res, 2 = half gelu, 3 = half qkv (segmented bias)
#define HSTG 4608  // uint32 per operand stage
#define GEMM_SMEM (4 * HSTG * 4)  // 73728 bytes

template <int EPI>
__global__ __launch_bounds__(256, 2) void gemm_h_kernel(
    const __half* __restrict__ A, const __half* __restrict__ Bt,
    const float* __restrict__ bias, const float* __restrict__ bias2,
    const float* __restrict__ bias3, const float* __restrict__ res,
    void* __restrict__ Cv, int M, int N, int K)
{
    extern __shared__ uint32_t smh[];
    const uint32_t smb = smem_u32(smh);
    const int tid = threadIdx.x;
    const int wid = tid >> 5, lane = tid & 31;
    const int g = lane >> 2, t = lane & 3;
    const int mi = lane >> 3, mr = lane & 7;
    const int rowoff = (mi & 1) * 8, koff = (mi >> 1) * 4;  // uint32 units
    const int warpM = (wid >> 2) * 64, warpN = (wid & 3) * 32;
    const int bm = blockIdx.y * 128, bn = blockIdx.x * 128;
    const int nch = K >> 6;

    const __half* Ab = A + (size_t)bm * K;
    const __half* Bb = Bt + (size_t)bn * K;

    const float* biasSeg = bias;
    int colShift = 0;
    if (EPI == 3) {
        const int seg = bn >> 10;
        biasSeg = (seg == 0) ? bias : (seg == 1) ? bias2 : bias3;
        colShift = seg << 10;
    }

    auto fill = [&](int st, int k0) {
#pragma unroll
        for (int r = 0; r < 4; r++) {
            const int idx = tid + 256 * r;
            const int row = idx >> 3, p = idx & 7;
            const uint32_t da = smb + (uint32_t)(st * HSTG + row * 36 + p * 4) * 4;
            const uint32_t db = smb + (uint32_t)((2 + st) * HSTG + row * 36 + p * 4) * 4;
            cp16(da, Ab + (size_t)row * K + k0 + p * 8);
            cp16(db, Bb + (size_t)row * K + k0 + p * 8);
        }
        CP_COMMIT();
    };

    fill(0, 0);

    float c[4][4][4];
#pragma unroll
    for (int i = 0; i < 4; i++)
#pragma unroll
        for (int j = 0; j < 4; j++)
#pragma unroll
            for (int q = 0; q < 4; q++) c[i][j][q] = 0.f;

    for (int ch = 0; ch < nch; ch++) {
        const int s = ch & 1;
        CP_WAIT0();
        __syncthreads();
        if (ch + 1 < nch) fill(s ^ 1, (ch + 1) << 6);

        const uint32_t Ast = smb + (uint32_t)(s * HSTG) * 4;
        const uint32_t Bst = smb + (uint32_t)((2 + s) * HSTG) * 4;

        uint32_t bf[4][8];
#pragma unroll
        for (int j = 0; j < 4; j++) {
            const uint32_t ab = Bst + (uint32_t)((warpN + 8 * j + mr) * 36 + mi * 4) * 4;
            ldsm4(bf[j], ab);
            ldsm4(bf[j] + 4, ab + 64);
        }
#pragma unroll
        for (int i = 0; i < 4; i++) {
            uint32_t af[4][4];
            const uint32_t aa = Ast + (uint32_t)((warpM + 16 * i + rowoff + mr) * 36 + koff) * 4;
#pragma unroll
            for (int km = 0; km < 4; km++) ldsm4(af[km], aa + km * 32u);
#pragma unroll
            for (int j = 0; j < 4; j++) {
                mma_f16(c[i][j], af[0], bf[j][0], bf[j][1]);
                mma_f16(c[i][j], af[1], bf[j][2], bf[j][3]);
                mma_f16(c[i][j], af[2], bf[j][4], bf[j][5]);
                mma_f16(c[i][j], af[3], bf[j][6], bf[j][7]);
            }
        }
    }

    // epilogue
#pragma unroll
    for (int i = 0; i < 4; i++) {
#pragma unroll
        for (int j = 0; j < 4; j++) {
            const int row0 = bm + warpM + 16 * i + g;
            const int col  = bn + warpN + 8 * j + 2 * t;
            const int bcol = (EPI == 3) ? (col - colShift) : col;
            const float b0 = biasSeg[bcol], b1 = biasSeg[bcol + 1];
            float v00 = c[i][j][0] + b0, v01 = c[i][j][1] + b1;
            float v10 = c[i][j][2] + b0, v11 = c[i][j][3] + b1;
            if (EPI == 1) {
                float* C = (float*)Cv;
                float2 r0 = *(const float2*)&res[(size_t)row0 * N + col];
                float2 r1 = *(const float2*)&res[(size_t)(row0 + 8) * N + col];
                *(float2*)&C[(size_t)row0 * N + col]       = make_float2(v00 + r0.x, v01 + r0.y);
                *(float2*)&C[(size_t)(row0 + 8) * N + col] = make_float2(v10 + r1.x, v11 + r1.y);
            } else if (EPI == 2) {
                __half* C = (__half*)Cv;
                *(__half2*)&C[(size_t)row0 * N + col] =
                    __floats2half2_rn(gelu_tanh(v00), gelu_tanh(v01));
                *(__half2*)&C[(size_t)(row0 + 8) * N + col] =
                    __floats2half2_rn(gelu_tanh(v10), gelu_tanh(v11));
            } else {  // EPI == 3
                __half* C = (__half*)Cv;
                *(__half2*)&C[(size_t)row0 * N + col]       = __floats2half2_rn(v00, v01);
                *(__half2*)&C[(size_t)(row0 + 8) * N + col] = __floats2half2_rn(v10, v11);
            }
        }
    }
}

// ---------------- tensor-core causal flash attention (R9 config + bh0) ----
__global__ __launch_bounds__(256, 2) void attn_tc_kernel(
    const __half* __restrict__ QKV, __half* __restrict__ Oh, int bh0)
{
    __shared__ uint32_t Qs[128][36];
    __shared__ uint32_t Ks[64][36];
    __shared__ uint32_t Vt[64][36];

    const int qt  = (int)gridDim.x - 1 - (int)blockIdx.x;
    const int bh  = blockIdx.y + bh0;
    const int b   = bh >> 4, h = bh & 15;
    const int tid = threadIdx.x, wid = tid >> 5, lane = tid & 31;
    const int g = lane >> 2, t = lane & 3;
    const int qb = qt * 128;
    const size_t bb = (size_t)b * T_SEQ;
    const int hq = h * HDIM, hk = hq + D_MODEL, hv = hq + 2 * D_MODEL;
    const int r0 = wid * 16;

#pragma unroll
    for (int r = 0; r < 4; r++) {
        const int lin = tid + 256 * r;
        const int row = lin >> 3, c = lin & 7;
        *(uint4*)&Qs[row][4 * c] =
            *(const uint4*)&QKV[(bb + qb + row) * QKV_N + hq + 8 * c];
    }
    __syncthreads();

    uint32_t qa[4][4];
    {
        const uint32_t qbase = smem_u32(Qs);
        const int mi = lane >> 3, mr = lane & 7;
        const int rowoff = (mi & 1) * 8, koff = (mi >> 1) * 4;
#pragma unroll
        for (int km = 0; km < 4; km++)
            ldsm4(qa[km], qbase + (uint32_t)((r0 + rowoff + mr) * 36 + km * 8 + koff) * 4);
    }

    float o[8][4];
#pragma unroll
    for (int j = 0; j < 8; j++)
#pragma unroll
        for (int q = 0; q < 4; q++) o[j][q] = 0.f;
    float m_g = -1e30f, m_g8 = -1e30f, l_g = 0.f, l_g8 = 0.f;
    const float SC = 0.18033688011112042f;  // (1/8) * log2(e)

    const uint32_t kbase = smem_u32(Ks), vbase = smem_u32(Vt);
    const int mi = lane >> 3, mr = lane & 7;

    const int nkt = 2 * qt + 2;
    for (int kt = 0; kt < nkt; kt++) {
        const int k0 = kt * 64;
#pragma unroll
        for (int r = 0; r < 2; r++) {
            const int lin = tid + 256 * r;
            const int row = lin >> 3, c = lin & 7;
            *(uint4*)&Ks[row][4 * c] =
                *(const uint4*)&QKV[(bb + k0 + row) * QKV_N + hk + 8 * c];
        }
        {
            const int kp = tid & 31, d8 = (tid >> 5) * 8;
            const __half* v0p = &QKV[(bb + k0 + 2 * kp) * QKV_N + hv + d8];
            uint4 v0 = *(const uint4*)v0p;
            uint4 v1 = *(const uint4*)(v0p + QKV_N);
            const ushort* a0 = (const ushort*)&v0;
            const ushort* a1 = (const ushort*)&v1;
#pragma unroll
            for (int i = 0; i < 8; i++)
                Vt[d8 + i][kp] = (uint32_t)a0[i] | ((uint32_t)a1[i] << 16);
        }
        __syncthreads();

        float s[8][4];
#pragma unroll
        for (int j = 0; j < 8; j++) {
            uint32_t kb[8];
            const uint32_t ab = kbase + (uint32_t)((8 * j + mr) * 36 + mi * 4) * 4;
            ldsm4(kb, ab);
            ldsm4(kb + 4, ab + 64);
            s[j][0] = s[j][1] = s[j][2] = s[j][3] = 0.f;
            mma_f16(s[j], qa[0], kb[0], kb[1]);
            mma_f16(s[j], qa[1], kb[2], kb[3]);
            mma_f16(s[j], qa[2], kb[4], kb[5]);
            mma_f16(s[j], qa[3], kb[6], kb[7]);
        }

        if (kt >= 2 * qt) {
            const int rg = qb + r0 + g;
#pragma unroll
            for (int j = 0; j < 8; j++) {
                const int col = k0 + 8 * j + 2 * t;
                if (col     > rg)     s[j][0] = -1e30f;
                if (col + 1 > rg)     s[j][1] = -1e30f;
                if (col     > rg + 8) s[j][2] = -1e30f;
                if (col + 1 > rg + 8) s[j][3] = -1e30f;
            }
        }

        float mg = -1e30f, mg8 = -1e30f;
#pragma unroll
        for (int j = 0; j < 8; j++) {
            mg  = fmaxf(mg,  fmaxf(s[j][0], s[j][1]));
            mg8 = fmaxf(mg8, fmaxf(s[j][2], s[j][3]));
        }
        mg  = fmaxf(mg,  __shfl_xor_sync(0xffffffffu, mg, 1));
        mg  = fmaxf(mg,  __shfl_xor_sync(0xffffffffu, mg, 2));
        mg8 = fmaxf(mg8, __shfl_xor_sync(0xffffffffu, mg8, 1));
        mg8 = fmaxf(mg8, __shfl_xor_sync(0xffffffffu, mg8, 2));
        const float mng  = fmaxf(m_g, mg);
        const float mng8 = fmaxf(m_g8, mg8);
        const float corr  = fast_ex2((m_g  - mng)  * SC);
        const float corr8 = fast_ex2((m_g8 - mng8) * SC);
        const float c1 = mng * SC, c2 = mng8 * SC;

        uint32_t pa[4][4];
        float sg = 0.f, sg8 = 0.f;
#pragma unroll
        for (int km = 0; km < 4; km++) {
#pragma unroll
            for (int jj = 0; jj < 2; jj++) {
                const int j = 2 * km + jj;
                uint32_t p01 = h2ex2(f22h2(s[j][0] * SC - c1, s[j][1] * SC - c1));
                uint32_t p23 = h2ex2(f22h2(s[j][2] * SC - c2, s[j][3] * SC - c2));
                pa[km][2 * jj]     = p01;
                pa[km][2 * jj + 1] = p23;
                float2 f01 = __half22float2(*(__half2*)&p01);
                float2 f23 = __half22float2(*(__half2*)&p23);
                sg  += f01.x + f01.y;
                sg8 += f23.x + f23.y;
            }
        }
        sg  += __shfl_xor_sync(0xffffffffu, sg, 1);
        sg  += __shfl_xor_sync(0xffffffffu, sg, 2);
        sg8 += __shfl_xor_sync(0xffffffffu, sg8, 1);
        sg8 += __shfl_xor_sync(0xffffffffu, sg8, 2);
        l_g  = l_g  * corr  + sg;
        l_g8 = l_g8 * corr8 + sg8;
        m_g = mng; m_g8 = mng8;
#pragma unroll
        for (int j = 0; j < 8; j++) {
            o[j][0] *= corr;  o[j][1] *= corr;
            o[j][2] *= corr8; o[j][3] *= corr8;
        }

#pragma unroll
        for (int j = 0; j < 8; j++) {
            uint32_t vb[8];
            const uint32_t ab = vbase + (uint32_t)((8 * j + mr) * 36 + mi * 4) * 4;
            ldsm4(vb, ab);
            ldsm4(vb + 4, ab + 64);
            mma_f16(o[j], pa[0], vb[0], vb[1]);
            mma_f16(o[j], pa[1], vb[2], vb[3]);
            mma_f16(o[j], pa[2], vb[4], vb[5]);
            mma_f16(o[j], pa[3], vb[6], vb[7]);
        }
        __syncthreads();
    }

    const float ig = 1.0f / l_g, ig8 = 1.0f / l_g8;
    __half* Og = Oh + (bb + qb + r0) * D_MODEL + hq;
#pragma unroll
    for (int j = 0; j < 8; j++) {
        const int col = 8 * j + 2 * t;
        *(__half2*)&Og[(size_t)g * D_MODEL + col] =
            __floats2half2_rn(o[j][0] * ig, o[j][1] * ig);
        *(__half2*)&Og[(size_t)(g + 8) * D_MODEL + col] =
            __floats2half2_rn(o[j][2] * ig8, o[j][3] * ig8);
    }
}

// ---------------- launch ----------------
extern "C" void kernel_launch(void* const* d_in, const int* in_sizes, int n_in,
                              void* d_out, int out_size)
{
    const float* x    = (const float*)d_in[0];
    const float* ln1s = (const float*)d_in[2];
    const float* ln1b = (const float*)d_in[3];
    const float* wq = (const float*)d_in[4];  const float* bq = (const float*)d_in[5];
    const float* wk = (const float*)d_in[6];  const float* bk = (const float*)d_in[7];
    const float* wv = (const float*)d_in[8];  const float* bv = (const float*)d_in[9];
    const float* wo = (const float*)d_in[10]; const float* bo = (const float*)d_in[11];
    const float* ln2s = (const float*)d_in[12];
    const float* ln2b = (const float*)d_in[13];
    const float* w1 = (const float*)d_in[14]; const float* b1 = (const float*)d_in[15];
    const float* w2 = (const float*)d_in[16]; const float* b2 = (const float*)d_in[17];
    float* out = (float*)d_out;

    __half *h1, *qkv, *att, *ff, *wqkvT, *woT, *w1T, *w2T;
    float *res;
    cudaGetSymbolAddress((void**)&h1,   g_h1);
    cudaGetSymbolAddress((void**)&qkv,  g_qkv);
    cudaGetSymbolAddress((void**)&att,  g_att);
    cudaGetSymbolAddress((void**)&res,  g_res);
    cudaGetSymbolAddress((void**)&ff,   g_ff);
    cudaGetSymbolAddress((void**)&wqkvT, g_wqkvT);
    cudaGetSymbolAddress((void**)&woT,  g_woT);
    cudaGetSymbolAddress((void**)&w1T,  g_w1T);
    cudaGetSymbolAddress((void**)&w2T,  g_w2T);

    cudaFuncSetAttribute(gemm_h_kernel<1>, cudaFuncAttributeMaxDynamicSharedMemorySize, GEMM_SMEM);
    cudaFuncSetAttribute(gemm_h_kernel<2>, cudaFuncAttributeMaxDynamicSharedMemorySize, GEMM_SMEM);
    cudaFuncSetAttribute(gemm_h_kernel<3>, cudaFuncAttributeMaxDynamicSharedMemorySize, GEMM_SMEM);

    cudaStream_t side;
    cudaStreamCreateWithFlags(&side, cudaStreamNonBlocking);
    cudaEvent_t ev0, evT1, evT2, evGA, evGB, evAA, evAB;
    cudaEventCreateWithFlags(&ev0,  cudaEventDisableTiming);
    cudaEventCreateWithFlags(&evT1, cudaEventDisableTiming);
    cudaEventCreateWithFlags(&evT2, cudaEventDisableTiming);
    cudaEventCreateWithFlags(&evGA, cudaEventDisableTiming);
    cudaEventCreateWithFlags(&evGB, cudaEventDisableTiming);
    cudaEventCreateWithFlags(&evAA, cudaEventDisableTiming);
    cudaEventCreateWithFlags(&evAB, cudaEventDisableTiming);

    const dim3 tb(32, 8);
    const dim3 gQKVh(QKV_N / 128, MHALF / 128);  // (24, 32) per batch-half
    const dim3 gDh(D_MODEL / 128, MHALF / 128);  // (8, 32)  per batch-half
    const dim3 gD(D_MODEL / 128, MROWS / 128);   // (8, 64)
    const dim3 gF(DFF / 128,     MROWS / 128);   // (32, 64)
    const dim3 gAttn(T_SEQ / 128, BATCH * NHEAD / 2);  // (8, 64) per half

    const size_t offD   = (size_t)MHALF * D_MODEL;
    const size_t offQKV = (size_t)MHALF * QKV_N;

    // side stream: weight transposes
    cudaEventRecord(ev0, 0);
    cudaStreamWaitEvent(side, ev0, 0);
    transpose_h_kernel<<<dim3(D_MODEL / 32, D_MODEL / 32), tb, 0, side>>>(wq, wqkvT, D_MODEL, D_MODEL);
    transpose_h_kernel<<<dim3(D_MODEL / 32, D_MODEL / 32), tb, 0, side>>>(wk, wqkvT + (size_t)D_MODEL * D_MODEL, D_MODEL, D_MODEL);
    transpose_h_kernel<<<dim3(D_MODEL / 32, D_MODEL / 32), tb, 0, side>>>(wv, wqkvT + (size_t)2 * D_MODEL * D_MODEL, D_MODEL, D_MODEL);
    cudaEventRecord(evT1, side);
    transpose_h_kernel<<<dim3(D_MODEL / 32, D_MODEL / 32), tb, 0, side>>>(wo, woT, D_MODEL, D_MODEL);
    transpose_h_kernel<<<dim3(DFF / 32, D_MODEL / 32), tb, 0, side>>>(w1, w1T, D_MODEL, DFF);
    transpose_h_kernel<<<dim3(D_MODEL / 32, DFF / 32), tb, 0, side>>>(w2, w2T, DFF, D_MODEL);
    cudaEventRecord(evT2, side);

    // main: LN1, then QKV GEMM split by batch halves
    ln_kernel<<<MROWS / 8, 256>>>(x, ln1s, ln1b, h1);
    cudaStreamWaitEvent(0, evT1, 0);
    gemm_h_kernel<3><<<gQKVh, 256, GEMM_SMEM>>>(h1, wqkvT, bq, bk, bv, nullptr, qkv, MHALF, QKV_N, D_MODEL);
    cudaEventRecord(evGA, 0);
    gemm_h_kernel<3><<<gQKVh, 256, GEMM_SMEM>>>(h1 + offD, wqkvT, bq, bk, bv, nullptr, qkv + offQKV, MHALF, QKV_N, D_MODEL);
    cudaEventRecord(evGB, 0);

    // side: attention halves (overlap with QKV-B and wo-A)
    cudaStreamWaitEvent(side, evGA, 0);
    attn_tc_kernel<<<gAttn, 256, 0, side>>>(qkv, att, 0);
    cudaEventRecord(evAA, side);
    cudaStreamWaitEvent(side, evGB, 0);
    attn_tc_kernel<<<gAttn, 256, 0, side>>>(qkv, att, 64);
    cudaEventRecord(evAB, side);

    // main: wo GEMM split (A-half overlaps attention B-half)
    cudaStreamWaitEvent(0, evT2, 0);
    cudaStreamWaitEvent(0, evAA, 0);
    gemm_h_kernel<1><<<gDh, 256, GEMM_SMEM>>>(att, woT, bo, nullptr, nullptr, x, res, MHALF, D_MODEL, D_MODEL);
    cudaStreamWaitEvent(0, evAB, 0);
    gemm_h_kernel<1><<<gDh, 256, GEMM_SMEM>>>(att + offD, woT, bo, nullptr, nullptr, x + offD, res + offD, MHALF, D_MODEL, D_MODEL);

    // main: LN2, FFN
    ln_kernel<<<MROWS / 8, 256>>>(res, ln2s, ln2b, h1);
    gemm_h_kernel<2><<<gF, 256, GEMM_SMEM>>>(h1, w1T, b1, nullptr, nullptr, nullptr, ff, MROWS, DFF, D_MODEL);
    gemm_h_kernel<1><<<gD, 256, GEMM_SMEM>>>(ff, w2T, b2, nullptr, nullptr, res, out, MROWS, D_MODEL, DFF);
}

// round 15
// speedup vs baseline: 1.0227x; 1.0227x over previous
#include <cuda_runtime.h>
#include <cuda_fp16.h>
#include <cstdint>
#include <cmath>

#define T_SEQ   1024
#define D_MODEL 1024
#define NHEAD   16
#define HDIM    64
#define DFF     4096
#define BATCH   8
#define MROWS   (BATCH * T_SEQ)
#define QKV_N   (3 * D_MODEL)

// ---------------- scratch (device globals: allocation-free) ----------------
__device__ __half g_h1 [(size_t)MROWS * D_MODEL];
__device__ __half g_qkv[(size_t)MROWS * QKV_N];
__device__ __half g_att[(size_t)MROWS * D_MODEL];
__device__ float  g_res[(size_t)MROWS * D_MODEL];
__device__ __half g_ff [(size_t)MROWS * DFF];
__device__ __half g_wqkvT[(size_t)QKV_N * D_MODEL];
__device__ __half g_woT[(size_t)D_MODEL * D_MODEL];
__device__ __half g_w1T[(size_t)DFF * D_MODEL];
__device__ __half g_w2T[(size_t)D_MODEL * DFF];

// ---------------- helpers ----------------
__device__ __forceinline__ uint32_t smem_u32(const void* p) {
    uint32_t a;
    asm("{ .reg .u64 t; cvta.to.shared.u64 t, %1; cvt.u32.u64 %0, t; }" : "=r"(a) : "l"(p));
    return a;
}
__device__ __forceinline__ float warp_sum(float v) {
#pragma unroll
    for (int o = 16; o > 0; o >>= 1) v += __shfl_xor_sync(0xffffffffu, v, o);
    return v;
}
__device__ __forceinline__ float fast_ex2(float x) {
    float y; asm("ex2.approx.f32 %0, %1;" : "=f"(y) : "f"(x)); return y;
}
__device__ __forceinline__ uint32_t h2ex2(uint32_t x) {
    uint32_t y; asm("ex2.approx.f16x2 %0, %1;" : "=r"(y) : "r"(x)); return y;
}
__device__ __forceinline__ float fast_tanh(float x) {
    float y; asm("tanh.approx.f32 %0, %1;" : "=f"(y) : "f"(x)); return y;
}
__device__ __forceinline__ float gelu_tanh(float x) {
    float x3 = x * x * x;
    float u  = 0.7978845608028654f * (x + 0.044715f * x3);
    return 0.5f * x * (1.0f + fast_tanh(u));
}
__device__ __forceinline__ void mma_f16(float* c, const uint32_t* a, uint32_t b0, uint32_t b1) {
    asm volatile(
        "mma.sync.aligned.m16n8k16.row.col.f32.f16.f16.f32 "
        "{%0,%1,%2,%3}, {%4,%5,%6,%7}, {%8,%9}, {%0,%1,%2,%3};\n"
        : "+f"(c[0]), "+f"(c[1]), "+f"(c[2]), "+f"(c[3])
        : "r"(a[0]), "r"(a[1]), "r"(a[2]), "r"(a[3]), "r"(b0), "r"(b1));
}
__device__ __forceinline__ void ldsm4(uint32_t* r, uint32_t addr) {
    asm volatile("ldmatrix.sync.aligned.m8n8.x4.shared.b16 {%0,%1,%2,%3}, [%4];"
        : "=r"(r[0]), "=r"(r[1]), "=r"(r[2]), "=r"(r[3]) : "r"(addr));
}
__device__ __forceinline__ uint32_t f22h2(float lo, float hi) {
    uint32_t u;
    asm("cvt.rn.f16x2.f32 %0, %1, %2;" : "=r"(u) : "f"(hi), "f"(lo));
    return u;
}
__device__ __forceinline__ void cp16(uint32_t dst, const void* src) {
    asm volatile("cp.async.cg.shared.global [%0], [%1], 16;" :: "r"(dst), "l"(src));
}
#define CP_COMMIT() asm volatile("cp.async.commit_group;" ::: "memory")
#define CP_WAIT0()  asm volatile("cp.async.wait_group 0;" ::: "memory")

// ---------------- weight transpose -> half: out[C][R] = (half)in[R][C] ----
__global__ __launch_bounds__(256) void transpose_h_kernel(
    const float* __restrict__ in, __half* __restrict__ out, int R, int C)
{
    __shared__ float t[32][33];
    const int bx = blockIdx.x * 32, by = blockIdx.y * 32;
    const int tx = threadIdx.x, ty = threadIdx.y;  // (32, 8)
#pragma unroll
    for (int i = 0; i < 4; i++)
        t[ty + 8 * i][tx] = in[(size_t)(by + ty + 8 * i) * C + bx + tx];
    __syncthreads();
#pragma unroll
    for (int i = 0; i < 4; i++)
        out[(size_t)(bx + ty + 8 * i) * R + by + tx] = __float2half_rn(t[tx][ty + 8 * i]);
}

// batched QKV transpose: z = 0/1/2 selects wq/wk/wv; all 3 run concurrently
__global__ __launch_bounds__(256) void transpose_qkv_kernel(
    const float* __restrict__ wq, const float* __restrict__ wk,
    const float* __restrict__ wv, __half* __restrict__ out)
{
    __shared__ float t[32][33];
    const int z = blockIdx.z;
    const float* in = (z == 0) ? wq : (z == 1) ? wk : wv;
    __half* o = out + (size_t)z * D_MODEL * D_MODEL;
    const int bx = blockIdx.x * 32, by = blockIdx.y * 32;
    const int tx = threadIdx.x, ty = threadIdx.y;  // (32, 8)
#pragma unroll
    for (int i = 0; i < 4; i++)
        t[ty + 8 * i][tx] = in[(size_t)(by + ty + 8 * i) * D_MODEL + bx + tx];
    __syncthreads();
#pragma unroll
    for (int i = 0; i < 4; i++)
        o[(size_t)(bx + ty + 8 * i) * D_MODEL + by + tx] = __float2half_rn(t[tx][ty + 8 * i]);
}

// ---------------- LayerNorm: warp-per-row, shuffle-only reduction ----------
__global__ __launch_bounds__(256) void ln_kernel(
    const float* __restrict__ x, const float* __restrict__ sc,
    const float* __restrict__ bi, __half* __restrict__ y)
{
    const int wid = threadIdx.x >> 5, lane = threadIdx.x & 31;
    const int row = blockIdx.x * 8 + wid;

    const float4* xp = (const float4*)(x + (size_t)row * D_MODEL);
    float4 v[8];
#pragma unroll
    for (int i = 0; i < 8; i++) v[i] = xp[lane + 32 * i];

    float s = 0.f, q = 0.f;
#pragma unroll
    for (int i = 0; i < 8; i++) {
        s += v[i].x + v[i].y + v[i].z + v[i].w;
        q += v[i].x * v[i].x + v[i].y * v[i].y + v[i].z * v[i].z + v[i].w * v[i].w;
    }
    s = warp_sum(s);
    q = warp_sum(q);
    const float mean = s * (1.0f / 1024.0f);
    const float rstd = rsqrtf(q * (1.0f / 1024.0f) - mean * mean + 1e-6f);

    const float4* scp = (const float4*)sc;
    const float4* bip = (const float4*)bi;
    uint2* yp = (uint2*)(y + (size_t)row * D_MODEL);
#pragma unroll
    for (int i = 0; i < 8; i++) {
        float4 sv = scp[lane + 32 * i];
        float4 bv = bip[lane + 32 * i];
        uint2 o;
        o.x = f22h2((v[i].x - mean) * rstd * sv.x + bv.x,
                    (v[i].y - mean) * rstd * sv.y + bv.y);
        o.y = f22h2((v[i].z - mean) * rstd * sv.z + bv.z,
                    (v[i].w - mean) * rstd * sv.w + bv.w);
        yp[lane + 32 * i] = o;
    }
}

// ---------------- fp16 GEMM, 128x128 CTA, 2-stage cp.async, 1 sync/chunk ----
// (exact R9/R13-winning configuration)
// EPI: 1 = f32 +res, 2 = half gelu, 3 = half qkv (segmented bias)
#define HSTG 4608  // uint32 per operand stage
#define GEMM_SMEM (4 * HSTG * 4)  // 73728 bytes

template <int EPI>
__global__ __launch_bounds__(256, 2) void gemm_h_kernel(
    const __half* __restrict__ A, const __half* __restrict__ Bt,
    const float* __restrict__ bias, const float* __restrict__ bias2,
    const float* __restrict__ bias3, const float* __restrict__ res,
    void* __restrict__ Cv, int M, int N, int K)
{
    extern __shared__ uint32_t smh[];
    const uint32_t smb = smem_u32(smh);
    const int tid = threadIdx.x;
    const int wid = tid >> 5, lane = tid & 31;
    const int g = lane >> 2, t = lane & 3;
    const int mi = lane >> 3, mr = lane & 7;
    const int rowoff = (mi & 1) * 8, koff = (mi >> 1) * 4;  // uint32 units
    const int warpM = (wid >> 2) * 64, warpN = (wid & 3) * 32;
    const int bm = blockIdx.y * 128, bn = blockIdx.x * 128;
    const int nch = K >> 6;

    const __half* Ab = A + (size_t)bm * K;
    const __half* Bb = Bt + (size_t)bn * K;

    const float* biasSeg = bias;
    int colShift = 0;
    if (EPI == 3) {
        const int seg = bn >> 10;
        biasSeg = (seg == 0) ? bias : (seg == 1) ? bias2 : bias3;
        colShift = seg << 10;
    }

    auto fill = [&](int st, int k0) {
#pragma unroll
        for (int r = 0; r < 4; r++) {
            const int idx = tid + 256 * r;
            const int row = idx >> 3, p = idx & 7;
            const uint32_t da = smb + (uint32_t)(st * HSTG + row * 36 + p * 4) * 4;
            const uint32_t db = smb + (uint32_t)((2 + st) * HSTG + row * 36 + p * 4) * 4;
            cp16(da, Ab + (size_t)row * K + k0 + p * 8);
            cp16(db, Bb + (size_t)row * K + k0 + p * 8);
        }
        CP_COMMIT();
    };

    fill(0, 0);

    float c[4][4][4];
#pragma unroll
    for (int i = 0; i < 4; i++)
#pragma unroll
        for (int j = 0; j < 4; j++)
#pragma unroll
            for (int q = 0; q < 4; q++) c[i][j][q] = 0.f;

    for (int ch = 0; ch < nch; ch++) {
        const int s = ch & 1;
        CP_WAIT0();
        __syncthreads();
        if (ch + 1 < nch) fill(s ^ 1, (ch + 1) << 6);

        const uint32_t Ast = smb + (uint32_t)(s * HSTG) * 4;
        const uint32_t Bst = smb + (uint32_t)((2 + s) * HSTG) * 4;

        uint32_t bf[4][8];
#pragma unroll
        for (int j = 0; j < 4; j++) {
            const uint32_t ab = Bst + (uint32_t)((warpN + 8 * j + mr) * 36 + mi * 4) * 4;
            ldsm4(bf[j], ab);
            ldsm4(bf[j] + 4, ab + 64);
        }
#pragma unroll
        for (int i = 0; i < 4; i++) {
            uint32_t af[4][4];
            const uint32_t aa = Ast + (uint32_t)((warpM + 16 * i + rowoff + mr) * 36 + koff) * 4;
#pragma unroll
            for (int km = 0; km < 4; km++) ldsm4(af[km], aa + km * 32u);
#pragma unroll
            for (int j = 0; j < 4; j++) {
                mma_f16(c[i][j], af[0], bf[j][0], bf[j][1]);
                mma_f16(c[i][j], af[1], bf[j][2], bf[j][3]);
                mma_f16(c[i][j], af[2], bf[j][4], bf[j][5]);
                mma_f16(c[i][j], af[3], bf[j][6], bf[j][7]);
            }
        }
    }

    // epilogue
#pragma unroll
    for (int i = 0; i < 4; i++) {
#pragma unroll
        for (int j = 0; j < 4; j++) {
            const int row0 = bm + warpM + 16 * i + g;
            const int col  = bn + warpN + 8 * j + 2 * t;
            const int bcol = (EPI == 3) ? (col - colShift) : col;
            const float b0 = biasSeg[bcol], b1 = biasSeg[bcol + 1];
            float v00 = c[i][j][0] + b0, v01 = c[i][j][1] + b1;
            float v10 = c[i][j][2] + b0, v11 = c[i][j][3] + b1;
            if (EPI == 1) {
                float* C = (float*)Cv;
                float2 r0 = *(const float2*)&res[(size_t)row0 * N + col];
                float2 r1 = *(const float2*)&res[(size_t)(row0 + 8) * N + col];
                *(float2*)&C[(size_t)row0 * N + col]       = make_float2(v00 + r0.x, v01 + r0.y);
                *(float2*)&C[(size_t)(row0 + 8) * N + col] = make_float2(v10 + r1.x, v11 + r1.y);
            } else if (EPI == 2) {
                __half* C = (__half*)Cv;
                *(__half2*)&C[(size_t)row0 * N + col] =
                    __floats2half2_rn(gelu_tanh(v00), gelu_tanh(v01));
                *(__half2*)&C[(size_t)(row0 + 8) * N + col] =
                    __floats2half2_rn(gelu_tanh(v10), gelu_tanh(v11));
            } else {  // EPI == 3
                __half* C = (__half*)Cv;
                *(__half2*)&C[(size_t)row0 * N + col]       = __floats2half2_rn(v00, v01);
                *(__half2*)&C[(size_t)(row0 + 8) * N + col] = __floats2half2_rn(v10, v11);
            }
        }
    }
}

// ---------------- tensor-core causal flash attention (R9 config) ----------
__global__ __launch_bounds__(256, 2) void attn_tc_kernel(
    const __half* __restrict__ QKV, __half* __restrict__ Oh)
{
    __shared__ uint32_t Qs[128][36];
    __shared__ uint32_t Ks[64][36];
    __shared__ uint32_t Vt[64][36];

    const int qt  = (int)gridDim.x - 1 - (int)blockIdx.x;
    const int bh  = blockIdx.y;
    const int b   = bh >> 4, h = bh & 15;
    const int tid = threadIdx.x, wid = tid >> 5, lane = tid & 31;
    const int g = lane >> 2, t = lane & 3;
    const int qb = qt * 128;
    const size_t bb = (size_t)b * T_SEQ;
    const int hq = h * HDIM, hk = hq + D_MODEL, hv = hq + 2 * D_MODEL;
    const int r0 = wid * 16;

#pragma unroll
    for (int r = 0; r < 4; r++) {
        const int lin = tid + 256 * r;
        const int row = lin >> 3, c = lin & 7;
        *(uint4*)&Qs[row][4 * c] =
            *(const uint4*)&QKV[(bb + qb + row) * QKV_N + hq + 8 * c];
    }
    __syncthreads();

    uint32_t qa[4][4];
    {
        const uint32_t qbase = smem_u32(Qs);
        const int mi = lane >> 3, mr = lane & 7;
        const int rowoff = (mi & 1) * 8, koff = (mi >> 1) * 4;
#pragma unroll
        for (int km = 0; km < 4; km++)
            ldsm4(qa[km], qbase + (uint32_t)((r0 + rowoff + mr) * 36 + km * 8 + koff) * 4);
    }

    float o[8][4];
#pragma unroll
    for (int j = 0; j < 8; j++)
#pragma unroll
        for (int q = 0; q < 4; q++) o[j][q] = 0.f;
    float m_g = -1e30f, m_g8 = -1e30f, l_g = 0.f, l_g8 = 0.f;
    const float SC = 0.18033688011112042f;  // (1/8) * log2(e)

    const uint32_t kbase = smem_u32(Ks), vbase = smem_u32(Vt);
    const int mi = lane >> 3, mr = lane & 7;

    const int nkt = 2 * qt + 2;
    for (int kt = 0; kt < nkt; kt++) {
        const int k0 = kt * 64;
#pragma unroll
        for (int r = 0; r < 2; r++) {
            const int lin = tid + 256 * r;
            const int row = lin >> 3, c = lin & 7;
            *(uint4*)&Ks[row][4 * c] =
                *(const uint4*)&QKV[(bb + k0 + row) * QKV_N + hk + 8 * c];
        }
        {
            const int kp = tid & 31, d8 = (tid >> 5) * 8;
            const __half* v0p = &QKV[(bb + k0 + 2 * kp) * QKV_N + hv + d8];
            uint4 v0 = *(const uint4*)v0p;
            uint4 v1 = *(const uint4*)(v0p + QKV_N);
            const ushort* a0 = (const ushort*)&v0;
            const ushort* a1 = (const ushort*)&v1;
#pragma unroll
            for (int i = 0; i < 8; i++)
                Vt[d8 + i][kp] = (uint32_t)a0[i] | ((uint32_t)a1[i] << 16);
        }
        __syncthreads();

        float s[8][4];
#pragma unroll
        for (int j = 0; j < 8; j++) {
            uint32_t kb[8];
            const uint32_t ab = kbase + (uint32_t)((8 * j + mr) * 36 + mi * 4) * 4;
            ldsm4(kb, ab);
            ldsm4(kb + 4, ab + 64);
            s[j][0] = s[j][1] = s[j][2] = s[j][3] = 0.f;
            mma_f16(s[j], qa[0], kb[0], kb[1]);
            mma_f16(s[j], qa[1], kb[2], kb[3]);
            mma_f16(s[j], qa[2], kb[4], kb[5]);
            mma_f16(s[j], qa[3], kb[6], kb[7]);
        }

        if (kt >= 2 * qt) {
            const int rg = qb + r0 + g;
#pragma unroll
            for (int j = 0; j < 8; j++) {
                const int col = k0 + 8 * j + 2 * t;
                if (col     > rg)     s[j][0] = -1e30f;
                if (col + 1 > rg)     s[j][1] = -1e30f;
                if (col     > rg + 8) s[j][2] = -1e30f;
                if (col + 1 > rg + 8) s[j][3] = -1e30f;
            }
        }

        float mg = -1e30f, mg8 = -1e30f;
#pragma unroll
        for (int j = 0; j < 8; j++) {
            mg  = fmaxf(mg,  fmaxf(s[j][0], s[j][1]));
            mg8 = fmaxf(mg8, fmaxf(s[j][2], s[j][3]));
        }
        mg  = fmaxf(mg,  __shfl_xor_sync(0xffffffffu, mg, 1));
        mg  = fmaxf(mg,  __shfl_xor_sync(0xffffffffu, mg, 2));
        mg8 = fmaxf(mg8, __shfl_xor_sync(0xffffffffu, mg8, 1));
        mg8 = fmaxf(mg8, __shfl_xor_sync(0xffffffffu, mg8, 2));
        const float mng  = fmaxf(m_g, mg);
        const float mng8 = fmaxf(m_g8, mg8);
        const float corr  = fast_ex2((m_g  - mng)  * SC);
        const float corr8 = fast_ex2((m_g8 - mng8) * SC);
        const float c1 = mng * SC, c2 = mng8 * SC;

        uint32_t pa[4][4];
        float sg = 0.f, sg8 = 0.f;
#pragma unroll
        for (int km = 0; km < 4; km++) {
#pragma unroll
            for (int jj = 0; jj < 2; jj++) {
                const int j = 2 * km + jj;
                uint32_t p01 = h2ex2(f22h2(s[j][0] * SC - c1, s[j][1] * SC - c1));
                uint32_t p23 = h2ex2(f22h2(s[j][2] * SC - c2, s[j][3] * SC - c2));
                pa[km][2 * jj]     = p01;
                pa[km][2 * jj + 1] = p23;
                float2 f01 = __half22float2(*(__half2*)&p01);
                float2 f23 = __half22float2(*(__half2*)&p23);
                sg  += f01.x + f01.y;
                sg8 += f23.x + f23.y;
            }
        }
        sg  += __shfl_xor_sync(0xffffffffu, sg, 1);
        sg  += __shfl_xor_sync(0xffffffffu, sg, 2);
        sg8 += __shfl_xor_sync(0xffffffffu, sg8, 1);
        sg8 += __shfl_xor_sync(0xffffffffu, sg8, 2);
        l_g  = l_g  * corr  + sg;
        l_g8 = l_g8 * corr8 + sg8;
        m_g = mng; m_g8 = mng8;
#pragma unroll
        for (int j = 0; j < 8; j++) {
            o[j][0] *= corr;  o[j][1] *= corr;
            o[j][2] *= corr8; o[j][3] *= corr8;
        }

#pragma unroll
        for (int j = 0; j < 8; j++) {
            uint32_t vb[8];
            const uint32_t ab = vbase + (uint32_t)((8 * j + mr) * 36 + mi * 4) * 4;
            ldsm4(vb, ab);
            ldsm4(vb + 4, ab + 64);
            mma_f16(o[j], pa[0], vb[0], vb[1]);
            mma_f16(o[j], pa[1], vb[2], vb[3]);
            mma_f16(o[j], pa[2], vb[4], vb[5]);
            mma_f16(o[j], pa[3], vb[6], vb[7]);
        }
        __syncthreads();
    }

    const float ig = 1.0f / l_g, ig8 = 1.0f / l_g8;
    __half* Og = Oh + (bb + qb + r0) * D_MODEL + hq;
#pragma unroll
    for (int j = 0; j < 8; j++) {
        const int col = 8 * j + 2 * t;
        *(__half2*)&Og[(size_t)g * D_MODEL + col] =
            __floats2half2_rn(o[j][0] * ig, o[j][1] * ig);
        *(__half2*)&Og[(size_t)(g + 8) * D_MODEL + col] =
            __floats2half2_rn(o[j][2] * ig8, o[j][3] * ig8);
    }
}

// ---------------- launch ----------------
extern "C" void kernel_launch(void* const* d_in, const int* in_sizes, int n_in,
                              void* d_out, int out_size)
{
    const float* x    = (const float*)d_in[0];
    const float* ln1s = (const float*)d_in[2];
    const float* ln1b = (const float*)d_in[3];
    const float* wq = (const float*)d_in[4];  const float* bq = (const float*)d_in[5];
    const float* wk = (const float*)d_in[6];  const float* bk = (const float*)d_in[7];
    const float* wv = (const float*)d_in[8];  const float* bv = (const float*)d_in[9];
    const float* wo = (const float*)d_in[10]; const float* bo = (const float*)d_in[11];
    const float* ln2s = (const float*)d_in[12];
    const float* ln2b = (const float*)d_in[13];
    const float* w1 = (const float*)d_in[14]; const float* b1 = (const float*)d_in[15];
    const float* w2 = (const float*)d_in[16]; const float* b2 = (const float*)d_in[17];
    float* out = (float*)d_out;

    __half *h1, *qkv, *att, *ff, *wqkvT, *woT, *w1T, *w2T;
    float *res;
    cudaGetSymbolAddress((void**)&h1,   g_h1);
    cudaGetSymbolAddress((void**)&qkv,  g_qkv);
    cudaGetSymbolAddress((void**)&att,  g_att);
    cudaGetSymbolAddress((void**)&res,  g_res);
    cudaGetSymbolAddress((void**)&ff,   g_ff);
    cudaGetSymbolAddress((void**)&wqkvT, g_wqkvT);
    cudaGetSymbolAddress((void**)&woT,  g_woT);
    cudaGetSymbolAddress((void**)&w1T,  g_w1T);
    cudaGetSymbolAddress((void**)&w2T,  g_w2T);

    cudaFuncSetAttribute(gemm_h_kernel<1>, cudaFuncAttributeMaxDynamicSharedMemorySize, GEMM_SMEM);
    cudaFuncSetAttribute(gemm_h_kernel<2>, cudaFuncAttributeMaxDynamicSharedMemorySize, GEMM_SMEM);
    cudaFuncSetAttribute(gemm_h_kernel<3>, cudaFuncAttributeMaxDynamicSharedMemorySize, GEMM_SMEM);

    cudaStream_t side;
    cudaStreamCreateWithFlags(&side, cudaStreamNonBlocking);
    cudaEvent_t ev0, ev1, ev2;
    cudaEventCreateWithFlags(&ev0, cudaEventDisableTiming);
    cudaEventCreateWithFlags(&ev1, cudaEventDisableTiming);
    cudaEventCreateWithFlags(&ev2, cudaEventDisableTiming);

    const dim3 tb(32, 8);
    const dim3 gQKV(QKV_N / 128, MROWS / 128);   // (24, 64)
    const dim3 gD(D_MODEL / 128, MROWS / 128);   // (8, 64)
    const dim3 gF(DFF / 128,     MROWS / 128);   // (32, 64)

    cudaEventRecord(ev0, 0);
    cudaStreamWaitEvent(side, ev0, 0);
    // one batched launch: wq/wk/wv transposed concurrently
    transpose_qkv_kernel<<<dim3(D_MODEL / 32, D_MODEL / 32, 3), tb, 0, side>>>(wq, wk, wv, wqkvT);
    cudaEventRecord(ev1, side);
    transpose_h_kernel<<<dim3(D_MODEL / 32, D_MODEL / 32), tb, 0, side>>>(wo, woT, D_MODEL, D_MODEL);
    transpose_h_kernel<<<dim3(DFF / 32, D_MODEL / 32), tb, 0, side>>>(w1, w1T, D_MODEL, DFF);
    transpose_h_kernel<<<dim3(D_MODEL / 32, DFF / 32), tb, 0, side>>>(w2, w2T, DFF, D_MODEL);
    cudaEventRecord(ev2, side);

    ln_kernel<<<MROWS / 8, 256>>>(x, ln1s, ln1b, h1);
    cudaStreamWaitEvent(0, ev1, 0);
    gemm_h_kernel<3><<<gQKV, 256, GEMM_SMEM>>>(h1, wqkvT, bq, bk, bv, nullptr, qkv, MROWS, QKV_N, D_MODEL);
    attn_tc_kernel<<<dim3(T_SEQ / 128, BATCH * NHEAD), 256>>>(qkv, att);
    cudaStreamWaitEvent(0, ev2, 0);
    gemm_h_kernel<1><<<gD, 256, GEMM_SMEM>>>(att, woT, bo, nullptr, nullptr, x, res, MROWS, D_MODEL, D_MODEL);
    ln_kernel<<<MROWS / 8, 256>>>(res, ln2s, ln2b, h1);
    gemm_h_kernel<2><<<gF, 256, GEMM_SMEM>>>(h1, w1T, b1, nullptr, nullptr, nullptr, ff, MROWS, DFF, D_MODEL);
    gemm_h_kernel<1><<<gD, 256, GEMM_SMEM>>>(ff, w2T, b2, nullptr, nullptr, res, out, MROWS, D_MODEL, DFF);
}

// round 16
// speedup vs baseline: 1.0516x; 1.0283x over previous
#include <cuda_runtime.h>
#include <cuda_fp16.h>
#include <cstdint>
#include <cmath>

#define T_SEQ   1024
#define D_MODEL 1024
#define NHEAD   16
#define HDIM    64
#define DFF     4096
#define BATCH   8
#define MROWS   (BATCH * T_SEQ)
#define QKV_N   (3 * D_MODEL)

// ---------------- scratch (device globals: allocation-free) ----------------
__device__ __half g_h1 [(size_t)MROWS * D_MODEL];
__device__ __half g_qkv[(size_t)MROWS * QKV_N];
__device__ __half g_att[(size_t)MROWS * D_MODEL];
__device__ float  g_res[(size_t)MROWS * D_MODEL];
__device__ __half g_ff [(size_t)MROWS * DFF];
__device__ __half g_wqkvT[(size_t)QKV_N * D_MODEL];
__device__ __half g_woT[(size_t)D_MODEL * D_MODEL];
__device__ __half g_w1T[(size_t)DFF * D_MODEL];
__device__ __half g_w2T[(size_t)D_MODEL * DFF];

// ---------------- helpers ----------------
__device__ __forceinline__ uint32_t smem_u32(const void* p) {
    uint32_t a;
    asm("{ .reg .u64 t; cvta.to.shared.u64 t, %1; cvt.u32.u64 %0, t; }" : "=r"(a) : "l"(p));
    return a;
}
__device__ __forceinline__ float warp_sum(float v) {
#pragma unroll
    for (int o = 16; o > 0; o >>= 1) v += __shfl_xor_sync(0xffffffffu, v, o);
    return v;
}
__device__ __forceinline__ float fast_ex2(float x) {
    float y; asm("ex2.approx.f32 %0, %1;" : "=f"(y) : "f"(x)); return y;
}
__device__ __forceinline__ uint32_t h2ex2(uint32_t x) {
    uint32_t y; asm("ex2.approx.f16x2 %0, %1;" : "=r"(y) : "r"(x)); return y;
}
__device__ __forceinline__ float fast_tanh(float x) {
    float y; asm("tanh.approx.f32 %0, %1;" : "=f"(y) : "f"(x)); return y;
}
__device__ __forceinline__ float gelu_tanh(float x) {
    float x3 = x * x * x;
    float u  = 0.7978845608028654f * (x + 0.044715f * x3);
    return 0.5f * x * (1.0f + fast_tanh(u));
}
__device__ __forceinline__ void mma_f16(float* c, const uint32_t* a, uint32_t b0, uint32_t b1) {
    asm volatile(
        "mma.sync.aligned.m16n8k16.row.col.f32.f16.f16.f32 "
        "{%0,%1,%2,%3}, {%4,%5,%6,%7}, {%8,%9}, {%0,%1,%2,%3};\n"
        : "+f"(c[0]), "+f"(c[1]), "+f"(c[2]), "+f"(c[3])
        : "r"(a[0]), "r"(a[1]), "r"(a[2]), "r"(a[3]), "r"(b0), "r"(b1));
}
__device__ __forceinline__ void ldsm4(uint32_t* r, uint32_t addr) {
    asm volatile("ldmatrix.sync.aligned.m8n8.x4.shared.b16 {%0,%1,%2,%3}, [%4];"
        : "=r"(r[0]), "=r"(r[1]), "=r"(r[2]), "=r"(r[3]) : "r"(addr));
}
__device__ __forceinline__ void ldsm4t(uint32_t* r, uint32_t addr) {
    asm volatile("ldmatrix.sync.aligned.m8n8.x4.trans.shared.b16 {%0,%1,%2,%3}, [%4];"
        : "=r"(r[0]), "=r"(r[1]), "=r"(r[2]), "=r"(r[3]) : "r"(addr));
}
__device__ __forceinline__ uint32_t f22h2(float lo, float hi) {
    uint32_t u;
    asm("cvt.rn.f16x2.f32 %0, %1, %2;" : "=r"(u) : "f"(hi), "f"(lo));
    return u;
}
__device__ __forceinline__ void cp16(uint32_t dst, const void* src) {
    asm volatile("cp.async.cg.shared.global [%0], [%1], 16;" :: "r"(dst), "l"(src));
}
#define CP_COMMIT() asm volatile("cp.async.commit_group;" ::: "memory")
#define CP_WAIT0()  asm volatile("cp.async.wait_group 0;" ::: "memory")

// ---------------- weight transpose -> half: out[C][R] = (half)in[R][C] ----
__global__ __launch_bounds__(256) void transpose_h_kernel(
    const float* __restrict__ in, __half* __restrict__ out, int R, int C)
{
    __shared__ float t[32][33];
    const int bx = blockIdx.x * 32, by = blockIdx.y * 32;
    const int tx = threadIdx.x, ty = threadIdx.y;  // (32, 8)
#pragma unroll
    for (int i = 0; i < 4; i++)
        t[ty + 8 * i][tx] = in[(size_t)(by + ty + 8 * i) * C + bx + tx];
    __syncthreads();
#pragma unroll
    for (int i = 0; i < 4; i++)
        out[(size_t)(bx + ty + 8 * i) * R + by + tx] = __float2half_rn(t[tx][ty + 8 * i]);
}

// batched QKV transpose: z = 0/1/2 selects wq/wk/wv
__global__ __launch_bounds__(256) void transpose_qkv_kernel(
    const float* __restrict__ wq, const float* __restrict__ wk,
    const float* __restrict__ wv, __half* __restrict__ out)
{
    __shared__ float t[32][33];
    const int z = blockIdx.z;
    const float* in = (z == 0) ? wq : (z == 1) ? wk : wv;
    __half* o = out + (size_t)z * D_MODEL * D_MODEL;
    const int bx = blockIdx.x * 32, by = blockIdx.y * 32;
    const int tx = threadIdx.x, ty = threadIdx.y;  // (32, 8)
#pragma unroll
    for (int i = 0; i < 4; i++)
        t[ty + 8 * i][tx] = in[(size_t)(by + ty + 8 * i) * D_MODEL + bx + tx];
    __syncthreads();
#pragma unroll
    for (int i = 0; i < 4; i++)
        o[(size_t)(bx + ty + 8 * i) * D_MODEL + by + tx] = __float2half_rn(t[tx][ty + 8 * i]);
}

// ---------------- LayerNorm: warp-per-row, shuffle-only reduction ----------
__global__ __launch_bounds__(256) void ln_kernel(
    const float* __restrict__ x, const float* __restrict__ sc,
    const float* __restrict__ bi, __half* __restrict__ y)
{
    const int wid = threadIdx.x >> 5, lane = threadIdx.x & 31;
    const int row = blockIdx.x * 8 + wid;

    const float4* xp = (const float4*)(x + (size_t)row * D_MODEL);
    float4 v[8];
#pragma unroll
    for (int i = 0; i < 8; i++) v[i] = xp[lane + 32 * i];

    float s = 0.f, q = 0.f;
#pragma unroll
    for (int i = 0; i < 8; i++) {
        s += v[i].x + v[i].y + v[i].z + v[i].w;
        q += v[i].x * v[i].x + v[i].y * v[i].y + v[i].z * v[i].z + v[i].w * v[i].w;
    }
    s = warp_sum(s);
    q = warp_sum(q);
    const float mean = s * (1.0f / 1024.0f);
    const float rstd = rsqrtf(q * (1.0f / 1024.0f) - mean * mean + 1e-6f);

    const float4* scp = (const float4*)sc;
    const float4* bip = (const float4*)bi;
    uint2* yp = (uint2*)(y + (size_t)row * D_MODEL);
#pragma unroll
    for (int i = 0; i < 8; i++) {
        float4 sv = scp[lane + 32 * i];
        float4 bv = bip[lane + 32 * i];
        uint2 o;
        o.x = f22h2((v[i].x - mean) * rstd * sv.x + bv.x,
                    (v[i].y - mean) * rstd * sv.y + bv.y);
        o.y = f22h2((v[i].z - mean) * rstd * sv.z + bv.z,
                    (v[i].w - mean) * rstd * sv.w + bv.w);
        yp[lane + 32 * i] = o;
    }
}

// ---------------- fp16 GEMM, 128x128 CTA, 2-stage cp.async, 1 sync/chunk ----
// (exact R9/R13-winning configuration)
// EPI: 1 = f32 +res, 2 = half gelu, 3 = half qkv (segmented bias)
#define HSTG 4608  // uint32 per operand stage
#define GEMM_SMEM (4 * HSTG * 4)  // 73728 bytes

template <int EPI>
__global__ __launch_bounds__(256, 2) void gemm_h_kernel(
    const __half* __restrict__ A, const __half* __restrict__ Bt,
    const float* __restrict__ bias, const float* __restrict__ bias2,
    const float* __restrict__ bias3, const float* __restrict__ res,
    void* __restrict__ Cv, int M, int N, int K)
{
    extern __shared__ uint32_t smh[];
    const uint32_t smb = smem_u32(smh);
    const int tid = threadIdx.x;
    const int wid = tid >> 5, lane = tid & 31;
    const int g = lane >> 2, t = lane & 3;
    const int mi = lane >> 3, mr = lane & 7;
    const int rowoff = (mi & 1) * 8, koff = (mi >> 1) * 4;  // uint32 units
    const int warpM = (wid >> 2) * 64, warpN = (wid & 3) * 32;
    const int bm = blockIdx.y * 128, bn = blockIdx.x * 128;
    const int nch = K >> 6;

    const __half* Ab = A + (size_t)bm * K;
    const __half* Bb = Bt + (size_t)bn * K;

    const float* biasSeg = bias;
    int colShift = 0;
    if (EPI == 3) {
        const int seg = bn >> 10;
        biasSeg = (seg == 0) ? bias : (seg == 1) ? bias2 : bias3;
        colShift = seg << 10;
    }

    auto fill = [&](int st, int k0) {
#pragma unroll
        for (int r = 0; r < 4; r++) {
            const int idx = tid + 256 * r;
            const int row = idx >> 3, p = idx & 7;
            const uint32_t da = smb + (uint32_t)(st * HSTG + row * 36 + p * 4) * 4;
            const uint32_t db = smb + (uint32_t)((2 + st) * HSTG + row * 36 + p * 4) * 4;
            cp16(da, Ab + (size_t)row * K + k0 + p * 8);
            cp16(db, Bb + (size_t)row * K + k0 + p * 8);
        }
        CP_COMMIT();
    };

    fill(0, 0);

    float c[4][4][4];
#pragma unroll
    for (int i = 0; i < 4; i++)
#pragma unroll
        for (int j = 0; j < 4; j++)
#pragma unroll
            for (int q = 0; q < 4; q++) c[i][j][q] = 0.f;

    for (int ch = 0; ch < nch; ch++) {
        const int s = ch & 1;
        CP_WAIT0();
        __syncthreads();
        if (ch + 1 < nch) fill(s ^ 1, (ch + 1) << 6);

        const uint32_t Ast = smb + (uint32_t)(s * HSTG) * 4;
        const uint32_t Bst = smb + (uint32_t)((2 + s) * HSTG) * 4;

        uint32_t bf[4][8];
#pragma unroll
        for (int j = 0; j < 4; j++) {
            const uint32_t ab = Bst + (uint32_t)((warpN + 8 * j + mr) * 36 + mi * 4) * 4;
            ldsm4(bf[j], ab);
            ldsm4(bf[j] + 4, ab + 64);
        }
#pragma unroll
        for (int i = 0; i < 4; i++) {
            uint32_t af[4][4];
            const uint32_t aa = Ast + (uint32_t)((warpM + 16 * i + rowoff + mr) * 36 + koff) * 4;
#pragma unroll
            for (int km = 0; km < 4; km++) ldsm4(af[km], aa + km * 32u);
#pragma unroll
            for (int j = 0; j < 4; j++) {
                mma_f16(c[i][j], af[0], bf[j][0], bf[j][1]);
                mma_f16(c[i][j], af[1], bf[j][2], bf[j][3]);
                mma_f16(c[i][j], af[2], bf[j][4], bf[j][5]);
                mma_f16(c[i][j], af[3], bf[j][6], bf[j][7]);
            }
        }
    }

    // epilogue
#pragma unroll
    for (int i = 0; i < 4; i++) {
#pragma unroll
        for (int j = 0; j < 4; j++) {
            const int row0 = bm + warpM + 16 * i + g;
            const int col  = bn + warpN + 8 * j + 2 * t;
            const int bcol = (EPI == 3) ? (col - colShift) : col;
            const float b0 = biasSeg[bcol], b1 = biasSeg[bcol + 1];
            float v00 = c[i][j][0] + b0, v01 = c[i][j][1] + b1;
            float v10 = c[i][j][2] + b0, v11 = c[i][j][3] + b1;
            if (EPI == 1) {
                float* C = (float*)Cv;
                float2 r0 = *(const float2*)&res[(size_t)row0 * N + col];
                float2 r1 = *(const float2*)&res[(size_t)(row0 + 8) * N + col];
                *(float2*)&C[(size_t)row0 * N + col]       = make_float2(v00 + r0.x, v01 + r0.y);
                *(float2*)&C[(size_t)(row0 + 8) * N + col] = make_float2(v10 + r1.x, v11 + r1.y);
            } else if (EPI == 2) {
                __half* C = (__half*)Cv;
                *(__half2*)&C[(size_t)row0 * N + col] =
                    __floats2half2_rn(gelu_tanh(v00), gelu_tanh(v01));
                *(__half2*)&C[(size_t)(row0 + 8) * N + col] =
                    __floats2half2_rn(gelu_tanh(v10), gelu_tanh(v11));
            } else {  // EPI == 3
                __half* C = (__half*)Cv;
                *(__half2*)&C[(size_t)row0 * N + col]       = __floats2half2_rn(v00, v01);
                *(__half2*)&C[(size_t)(row0 + 8) * N + col] = __floats2half2_rn(v10, v11);
            }
        }
    }
}

// ---------------- tensor-core causal flash attention ----------------
// K and V tiles raw-copied via cp.async (double-buffered, 1 sync/tile);
// V b-frags via ldmatrix.trans (no register transpose).
// dyn smem (uint32): Qs[0,4608) | st0: K[4608,6912) V[6912,9216)
//                              | st1: K[9216,11520) V[11520,13824)
#define ATTN_SMEM (13824 * 4)  // 55296 bytes

__global__ __launch_bounds__(256, 2) void attn_tc_kernel(
    const __half* __restrict__ QKV, __half* __restrict__ Oh)
{
    extern __shared__ uint32_t dynsm[];
    uint32_t* Qs = dynsm;  // [128][36]

    const int qt  = (int)gridDim.x - 1 - (int)blockIdx.x;
    const int bh  = blockIdx.y;
    const int b   = bh >> 4, h = bh & 15;
    const int tid = threadIdx.x, wid = tid >> 5, lane = tid & 31;
    const int g = lane >> 2, t = lane & 3;
    const int qb = qt * 128;
    const size_t bb = (size_t)b * T_SEQ;
    const int hq = h * HDIM, hk = hq + D_MODEL, hv = hq + 2 * D_MODEL;
    const int r0 = wid * 16;
    const uint32_t smb = smem_u32(dynsm);

    // async copy of K+V tile kt into stage st (raw row-major copies)
    auto load_kv = [&](int kt, int st) {
        const int k0 = kt * 64;
        const uint32_t kb = smb + (uint32_t)(4608 + st * 4608) * 4;
        const uint32_t vb = kb + 2304u * 4;
#pragma unroll
        for (int r = 0; r < 2; r++) {
            const int idx = tid + 256 * r;
            const int row = idx >> 3, p = idx & 7;
            const __half* src = &QKV[(bb + k0 + row) * QKV_N + p * 8];
            cp16(kb + (uint32_t)(row * 36 + p * 4) * 4, src + hk);
            cp16(vb + (uint32_t)(row * 36 + p * 4) * 4, src + hv);
        }
        CP_COMMIT();
    };

    load_kv(0, 0);

    // Q tile load (sync)
#pragma unroll
    for (int r = 0; r < 4; r++) {
        const int lin = tid + 256 * r;
        const int row = lin >> 3, c = lin & 7;
        *(uint4*)&Qs[row * 36 + 4 * c] =
            *(const uint4*)&QKV[(bb + qb + row) * QKV_N + hq + 8 * c];
    }
    __syncthreads();

    uint32_t qa[4][4];
    {
        const int mi = lane >> 3, mr = lane & 7;
        const int rowoff = (mi & 1) * 8, koff = (mi >> 1) * 4;
#pragma unroll
        for (int km = 0; km < 4; km++)
            ldsm4(qa[km], smb + (uint32_t)((r0 + rowoff + mr) * 36 + km * 8 + koff) * 4);
    }

    float o[8][4];
#pragma unroll
    for (int j = 0; j < 8; j++)
#pragma unroll
        for (int q = 0; q < 4; q++) o[j][q] = 0.f;
    float m_g = -1e30f, m_g8 = -1e30f, l_g = 0.f, l_g8 = 0.f;
    const float SC = 0.18033688011112042f;  // (1/8) * log2(e)
    const int mi = lane >> 3, mr = lane & 7;

    const int nkt = 2 * qt + 2;
    for (int kt = 0; kt < nkt; kt++) {
        const int st = kt & 1;
        CP_WAIT0();          // K/V tile kt resident
        __syncthreads();     // stage st^1 reads (iter kt-1) complete
        if (kt + 1 < nkt) load_kv(kt + 1, st ^ 1);

        const uint32_t kbase = smb + (uint32_t)(4608 + st * 4608) * 4;
        const uint32_t vbase = kbase + 2304u * 4;
        const int k0 = kt * 64;

        float s[8][4];
#pragma unroll
        for (int j = 0; j < 8; j++) {
            uint32_t kb[8];
            const uint32_t ab = kbase + (uint32_t)((8 * j + mr) * 36 + mi * 4) * 4;
            ldsm4(kb, ab);
            ldsm4(kb + 4, ab + 64);
            s[j][0] = s[j][1] = s[j][2] = s[j][3] = 0.f;
            mma_f16(s[j], qa[0], kb[0], kb[1]);
            mma_f16(s[j], qa[1], kb[2], kb[3]);
            mma_f16(s[j], qa[2], kb[4], kb[5]);
            mma_f16(s[j], qa[3], kb[6], kb[7]);
        }

        if (kt >= 2 * qt) {
            const int rg = qb + r0 + g;
#pragma unroll
            for (int j = 0; j < 8; j++) {
                const int col = k0 + 8 * j + 2 * t;
                if (col     > rg)     s[j][0] = -1e30f;
                if (col + 1 > rg)     s[j][1] = -1e30f;
                if (col     > rg + 8) s[j][2] = -1e30f;
                if (col + 1 > rg + 8) s[j][3] = -1e30f;
            }
        }

        float mg = -1e30f, mg8 = -1e30f;
#pragma unroll
        for (int j = 0; j < 8; j++) {
            mg  = fmaxf(mg,  fmaxf(s[j][0], s[j][1]));
            mg8 = fmaxf(mg8, fmaxf(s[j][2], s[j][3]));
        }
        mg  = fmaxf(mg,  __shfl_xor_sync(0xffffffffu, mg, 1));
        mg  = fmaxf(mg,  __shfl_xor_sync(0xffffffffu, mg, 2));
        mg8 = fmaxf(mg8, __shfl_xor_sync(0xffffffffu, mg8, 1));
        mg8 = fmaxf(mg8, __shfl_xor_sync(0xffffffffu, mg8, 2));
        const float mng  = fmaxf(m_g, mg);
        const float mng8 = fmaxf(m_g8, mg8);
        const float corr  = fast_ex2((m_g  - mng)  * SC);
        const float corr8 = fast_ex2((m_g8 - mng8) * SC);
        const float c1 = mng * SC, c2 = mng8 * SC;

        uint32_t pa[4][4];
        float sg = 0.f, sg8 = 0.f;
#pragma unroll
        for (int km = 0; km < 4; km++) {
#pragma unroll
            for (int jj = 0; jj < 2; jj++) {
                const int j = 2 * km + jj;
                uint32_t p01 = h2ex2(f22h2(s[j][0] * SC - c1, s[j][1] * SC - c1));
                uint32_t p23 = h2ex2(f22h2(s[j][2] * SC - c2, s[j][3] * SC - c2));
                pa[km][2 * jj]     = p01;
                pa[km][2 * jj + 1] = p23;
                float2 f01 = __half22float2(*(__half2*)&p01);
                float2 f23 = __half22float2(*(__half2*)&p23);
                sg  += f01.x + f01.y;
                sg8 += f23.x + f23.y;
            }
        }
        sg  += __shfl_xor_sync(0xffffffffu, sg, 1);
        sg  += __shfl_xor_sync(0xffffffffu, sg, 2);
        sg8 += __shfl_xor_sync(0xffffffffu, sg8, 1);
        sg8 += __shfl_xor_sync(0xffffffffu, sg8, 2);
        l_g  = l_g  * corr  + sg;
        l_g8 = l_g8 * corr8 + sg8;
        m_g = mng; m_g8 = mng8;
#pragma unroll
        for (int j = 0; j < 8; j++) {
            o[j][0] *= corr;  o[j][1] *= corr;
            o[j][2] *= corr8; o[j][3] *= corr8;
        }

        // O += P V : b-frags via ldmatrix.trans on row-major V
        const uint32_t va0 = vbase + (uint32_t)(lane * 36) * 4;
        const uint32_t va1 = vbase + (uint32_t)((32 + lane) * 36) * 4;
#pragma unroll
        for (int j = 0; j < 8; j++) {
            uint32_t vb[8];
            ldsm4t(vb,     va0 + 16u * j);
            ldsm4t(vb + 4, va1 + 16u * j);
            mma_f16(o[j], pa[0], vb[0], vb[1]);
            mma_f16(o[j], pa[1], vb[2], vb[3]);
            mma_f16(o[j], pa[2], vb[4], vb[5]);
            mma_f16(o[j], pa[3], vb[6], vb[7]);
        }
    }

    const float ig = 1.0f / l_g, ig8 = 1.0f / l_g8;
    __half* Og = Oh + (bb + qb + r0) * D_MODEL + hq;
#pragma unroll
    for (int j = 0; j < 8; j++) {
        const int col = 8 * j + 2 * t;
        *(__half2*)&Og[(size_t)g * D_MODEL + col] =
            __floats2half2_rn(o[j][0] * ig, o[j][1] * ig);
        *(__half2*)&Og[(size_t)(g + 8) * D_MODEL + col] =
            __floats2half2_rn(o[j][2] * ig8, o[j][3] * ig8);
    }
}

// ---------------- launch ----------------
extern "C" void kernel_launch(void* const* d_in, const int* in_sizes, int n_in,
                              void* d_out, int out_size)
{
    const float* x    = (const float*)d_in[0];
    const float* ln1s = (const float*)d_in[2];
    const float* ln1b = (const float*)d_in[3];
    const float* wq = (const float*)d_in[4];  const float* bq = (const float*)d_in[5];
    const float* wk = (const float*)d_in[6];  const float* bk = (const float*)d_in[7];
    const float* wv = (const float*)d_in[8];  const float* bv = (const float*)d_in[9];
    const float* wo = (const float*)d_in[10]; const float* bo = (const float*)d_in[11];
    const float* ln2s = (const float*)d_in[12];
    const float* ln2b = (const float*)d_in[13];
    const float* w1 = (const float*)d_in[14]; const float* b1 = (const float*)d_in[15];
    const float* w2 = (const float*)d_in[16]; const float* b2 = (const float*)d_in[17];
    float* out = (float*)d_out;

    __half *h1, *qkv, *att, *ff, *wqkvT, *woT, *w1T, *w2T;
    float *res;
    cudaGetSymbolAddress((void**)&h1,   g_h1);
    cudaGetSymbolAddress((void**)&qkv,  g_qkv);
    cudaGetSymbolAddress((void**)&att,  g_att);
    cudaGetSymbolAddress((void**)&res,  g_res);
    cudaGetSymbolAddress((void**)&ff,   g_ff);
    cudaGetSymbolAddress((void**)&wqkvT, g_wqkvT);
    cudaGetSymbolAddress((void**)&woT,  g_woT);
    cudaGetSymbolAddress((void**)&w1T,  g_w1T);
    cudaGetSymbolAddress((void**)&w2T,  g_w2T);

    cudaFuncSetAttribute(gemm_h_kernel<1>, cudaFuncAttributeMaxDynamicSharedMemorySize, GEMM_SMEM);
    cudaFuncSetAttribute(gemm_h_kernel<2>, cudaFuncAttributeMaxDynamicSharedMemorySize, GEMM_SMEM);
    cudaFuncSetAttribute(gemm_h_kernel<3>, cudaFuncAttributeMaxDynamicSharedMemorySize, GEMM_SMEM);
    cudaFuncSetAttribute(attn_tc_kernel,   cudaFuncAttributeMaxDynamicSharedMemorySize, ATTN_SMEM);

    cudaStream_t side;
    cudaStreamCreateWithFlags(&side, cudaStreamNonBlocking);
    cudaEvent_t ev0, ev1, ev2;
    cudaEventCreateWithFlags(&ev0, cudaEventDisableTiming);
    cudaEventCreateWithFlags(&ev1, cudaEventDisableTiming);
    cudaEventCreateWithFlags(&ev2, cudaEventDisableTiming);

    const dim3 tb(32, 8);
    const dim3 gQKV(QKV_N / 128, MROWS / 128);   // (24, 64)
    const dim3 gD(D_MODEL / 128, MROWS / 128);   // (8, 64)
    const dim3 gF(DFF / 128,     MROWS / 128);   // (32, 64)

    cudaEventRecord(ev0, 0);
    cudaStreamWaitEvent(side, ev0, 0);
    transpose_qkv_kernel<<<dim3(D_MODEL / 32, D_MODEL / 32, 3), tb, 0, side>>>(wq, wk, wv, wqkvT);
    cudaEventRecord(ev1, side);
    transpose_h_kernel<<<dim3(D_MODEL / 32, D_MODEL / 32), tb, 0, side>>>(wo, woT, D_MODEL, D_MODEL);
    transpose_h_kernel<<<dim3(DFF / 32, D_MODEL / 32), tb, 0, side>>>(w1, w1T, D_MODEL, DFF);
    transpose_h_kernel<<<dim3(D_MODEL / 32, DFF / 32), tb, 0, side>>>(w2, w2T, DFF, D_MODEL);
    cudaEventRecord(ev2, side);

    ln_kernel<<<MROWS / 8, 256>>>(x, ln1s, ln1b, h1);
    cudaStreamWaitEvent(0, ev1, 0);
    gemm_h_kernel<3><<<gQKV, 256, GEMM_SMEM>>>(h1, wqkvT, bq, bk, bv, nullptr, qkv, MROWS, QKV_N, D_MODEL);
    attn_tc_kernel<<<dim3(T_SEQ / 128, BATCH * NHEAD), 256, ATTN_SMEM>>>(qkv, att);
    cudaStreamWaitEvent(0, ev2, 0);
    gemm_h_kernel<1><<<gD, 256, GEMM_SMEM>>>(att, woT, bo, nullptr, nullptr, x, res, MROWS, D_MODEL, D_MODEL);
    ln_kernel<<<MROWS / 8, 256>>>(res, ln2s, ln2b, h1);
    gemm_h_kernel<2><<<gF, 256, GEMM_SMEM>>>(h1, w1T, b1, nullptr, nullptr, nullptr, ff, MROWS, DFF, D_MODEL);
    gemm_h_kernel<1><<<gD, 256, GEMM_SMEM>>>(ff, w2T, b2, nullptr, nullptr, res, out, MROWS, D_MODEL, DFF);
}